// round 14
// baseline (speedup 1.0000x reference)
#include <cuda_runtime.h>
#include <cuda_fp16.h>
#include <cstdint>

// Problem constants (B=4, S=2048, EMB=1024, HEADS=16, HEAD_DIM=64)
#define TOK   8192
#define EMB_  1024
#define NHEAD 16
#define HDIM  64
#define TILEB 16384          // one 128-row x 128-byte (64 fp16) tile

// ---------------------------------------------------------------------------
// Scratch (device globals). Tiled-swizzled fp16 (GEMM operand layout):
// element (row, col) -> tile (row>>7, col>>6), inside: byte
//   (row&127)*128 + (((col&63)>>3) ^ (row&7))*16 + (col&7)*2
// Plus fp16 row-major q/k/v intermediates.
// ---------------------------------------------------------------------------
__device__ __half g_vh[TOK * EMB_];
__device__ __half g_kh[TOK * EMB_];
__device__ __half g_qh[TOK * EMB_];
__device__ __half g_wvh[EMB_ * EMB_];
__device__ __half g_wkh[EMB_ * EMB_];
__device__ __half g_wqh[EMB_ * EMB_];
__device__ __half g_woh[EMB_ * EMB_];
__device__ __half g_ah[TOK * EMB_];
__device__ __half g_vo[TOK * EMB_];
__device__ __half g_ko[TOK * EMB_];
__device__ __half g_qo[TOK * EMB_];

// ---------------------------------------------------------------------------
// PTX helpers
// ---------------------------------------------------------------------------
__device__ __forceinline__ uint32_t smem_u32(const void* p) {
    uint32_t a;
    asm("{ .reg .u64 t; cvta.to.shared.u64 t, %1; cvt.u32.u64 %0, t; }"
        : "=r"(a) : "l"(p));
    return a;
}

__device__ __forceinline__ uint32_t pack_h2(float a, float b) {
    const __half2 h = __floats2half2_rn(a, b);
    return *(const uint32_t*)&h;
}

#define MBAR_INIT(addr, cnt) \
    asm volatile("mbarrier.init.shared.b64 [%0], %1;" :: "r"(addr), "r"(cnt) : "memory")
#define MBAR_EXPECT_TX(addr, bytes) \
    asm volatile("mbarrier.arrive.expect_tx.shared.b64 _, [%0], %1;" \
                 :: "r"(addr), "r"(bytes) : "memory")
#define MBAR_WAIT(addr, parity) do { \
    uint32_t _m = (addr), _p = (parity), _done; \
    asm volatile("{ .reg .pred p; mbarrier.try_wait.parity.acquire.cta.shared::cta.b64 p, [%1], %2; selp.b32 %0, 1, 0, p; }" \
                 : "=r"(_done) : "r"(_m), "r"(_p) : "memory"); \
    if (!_done) { \
        asm volatile("{ .reg .pred P1; WL_%=: mbarrier.try_wait.parity.acquire.cta.shared::cta.b64 P1, [%0], %1, 0x989680; @P1 bra.uni WD_%=; bra.uni WL_%=; WD_%=: }" \
                     :: "r"(_m), "r"(_p) : "memory"); \
    } \
} while (0)

__device__ __forceinline__ void bulk_g2s(uint32_t dst, const void* src,
                                         uint32_t bytes, uint32_t mbar) {
    asm volatile(
        "cp.async.bulk.shared::cluster.global.mbarrier::complete_tx::bytes [%0], [%1], %2, [%3];"
        :: "r"(dst), "l"(src), "r"(bytes), "r"(mbar) : "memory");
}

#define LDSM4(R, addr) \
    asm volatile("ldmatrix.sync.aligned.m8n8.x4.shared.b16 {%0,%1,%2,%3}, [%4];" \
        : "=r"((R)[0]), "=r"((R)[1]), "=r"((R)[2]), "=r"((R)[3]) : "r"(addr))

#define MMA16816(D, A, B0, B1) \
    asm volatile("mma.sync.aligned.m16n8k16.row.col.f32.f16.f16.f32 " \
        "{%0,%1,%2,%3}, {%4,%5,%6,%7}, {%8,%9}, {%0,%1,%2,%3};" \
        : "+f"((D)[0]), "+f"((D)[1]), "+f"((D)[2]), "+f"((D)[3]) \
        : "r"((A)[0]), "r"((A)[1]), "r"((A)[2]), "r"((A)[3]), "r"(B0), "r"(B1))

// ---------------------------------------------------------------------------
// Conversion: fp32 row-major -> fp16 (round) in tiled-swizzled layout.
// ---------------------------------------------------------------------------
__device__ __forceinline__ void round_store(const float* __restrict__ src,
                                            __half* __restrict__ hi, int gid)
{
    const int row = gid >> 7;
    const int chunk = gid & 127;
    const int col0 = chunk << 3;
    const int kc = col0 >> 6;
    const int c16 = (col0 >> 3) & 7;

    const float4* sp = (const float4*)(src + (size_t)row * EMB_ + col0);
    float x[8];
    *(float4*)&x[0] = sp[0];
    *(float4*)&x[4] = sp[1];

    uint32_t hw[4];
#pragma unroll
    for (int i = 0; i < 4; i++)
        hw[i] = pack_h2(x[2 * i], x[2 * i + 1]);

    const size_t off = (((size_t)(row >> 7) * 16 + kc) << 14)
                     + (row & 127) * 128 + ((c16 ^ (row & 7)) << 4);
    *(uint4*)((char*)hi + off) = make_uint4(hw[0], hw[1], hw[2], hw[3]);
}

struct ConvArgs {
    const float* src[4];
    __half* hi[4];
};

__global__ __launch_bounds__(256)
void conv_act(ConvArgs a)   // grid (4096, 3)
{
    const int z = blockIdx.y;
    const int gid = blockIdx.x * 256 + threadIdx.x;
    round_store(a.src[z], a.hi[z], gid);
}

__global__ __launch_bounds__(256)
void conv_w(ConvArgs a)     // grid (512, 4)
{
    const int z = blockIdx.y;
    const int gid = blockIdx.x * 256 + threadIdx.x;
    round_store(a.src[z], a.hi[z], gid);
}

// ---------------------------------------------------------------------------
// 1-term fp16 HMMA GEMM core, fat-warp layout:
// CTA tile 128x128, 4 warps in 2m x 2n, warp tile 64x64 (128 acc regs),
// K-chunk 64, 3-stage bulk pipeline, 2 CTAs/SM by smem.
// Per-chunk SMEM reads: 64KB/CTA (each fragment read by 2 warps, was 3x more).
// OUT==0: fp32 C; OUT==1: fp16 C (row-major).
// ---------------------------------------------------------------------------
#define STAGEB (2 * TILEB)              // 32768
#define GSMEM  (1024 + 3 * STAGEB)      // 99328

template <int OUT>
__device__ __forceinline__
void gemm_core1(const __half* __restrict__ Ah, const __half* __restrict__ Bh,
                const float* __restrict__ bias, void* __restrict__ Cv,
                char* smem)
{
    const uint32_t sb = smem_u32(smem);
    const int tid = threadIdx.x;
    const int wid = tid >> 5, lane = tid & 31;
    const int ntb = blockIdx.x, mtb = blockIdx.y;
    const int wm = wid >> 1, wn = wid & 1;          // 2m x 2n

    if (tid == 0) {
        MBAR_INIT(sb + 0, 1);
        MBAR_INIT(sb + 8, 1);
        MBAR_INIT(sb + 16, 1);
    }
    __syncthreads();

    const uint32_t st0 = sb + 1024;
    const char* aH = (const char*)Ah + ((size_t)mtb * 16 << 14);
    const char* bH = (const char*)Bh + ((size_t)ntb * 16 << 14);

    auto load_stage = [&](int kc, int s) {
        const uint32_t full = sb + 8 * s;
        MBAR_EXPECT_TX(full, STAGEB);
        const uint32_t d = st0 + s * STAGEB;
        const size_t o = (size_t)kc << 14;
        bulk_g2s(d,         aH + o, TILEB, full);
        bulk_g2s(d + TILEB, bH + o, TILEB, full);
    };

    if (tid == 0) {
        load_stage(0, 0);
        load_stage(1, 1);
        load_stage(2, 2);
    }

    float acc[4][8][4];
#pragma unroll
    for (int a = 0; a < 4; a++)
#pragma unroll
        for (int b = 0; b < 8; b++)
#pragma unroll
            for (int c = 0; c < 4; c++) acc[a][b][c] = 0.0f;

    const uint32_t la7 = lane & 7;
    const uint32_t a_row = (uint32_t)(wm * 64 + (lane & 15)) * 128;
    const uint32_t a_sel = (lane >> 4);
    const uint32_t b_row = (uint32_t)(wn * 64 + ((lane >> 4) & 1) * 8 + (lane & 7)) * 128;
    const uint32_t b_sel = ((lane >> 3) & 1);

    int s = 0, par = 0;
    for (int kc = 0; kc < 16; kc++) {
        MBAR_WAIT(sb + 8 * s, par);

        const uint32_t st = st0 + s * STAGEB;
        const uint32_t tAH = st;
        const uint32_t tBH = st + TILEB;

#pragma unroll
        for (int ks = 0; ks < 4; ks++) {
            const uint32_t ca = ((uint32_t)(ks * 2) + a_sel) ^ la7;
            const uint32_t cb = ((uint32_t)(ks * 2) + b_sel) ^ la7;
            uint32_t ah[4][4], bh[4][4];
#pragma unroll
            for (int m2 = 0; m2 < 4; m2++)
                LDSM4(ah[m2], tAH + a_row + m2 * 2048 + ca * 16);
#pragma unroll
            for (int n2 = 0; n2 < 4; n2++)
                LDSM4(bh[n2], tBH + b_row + n2 * 2048 + cb * 16);
#pragma unroll
            for (int m2 = 0; m2 < 4; m2++)
#pragma unroll
                for (int n2 = 0; n2 < 4; n2++) {
                    MMA16816(acc[m2][n2 * 2 + 0], ah[m2], bh[n2][0], bh[n2][1]);
                    MMA16816(acc[m2][n2 * 2 + 1], ah[m2], bh[n2][2], bh[n2][3]);
                }
        }
        __syncthreads();
        if (tid == 0 && kc + 3 < 16) load_stage(kc + 3, s);
        if (++s == 3) { s = 0; par ^= 1; }
    }

    const int rbase = mtb * 128 + wm * 64 + (lane >> 2);
    const int cbase = ntb * 128 + wn * 64 + (lane & 3) * 2;
#pragma unroll
    for (int m2 = 0; m2 < 4; m2++)
#pragma unroll
        for (int nt2 = 0; nt2 < 8; nt2++) {
            const int col = cbase + nt2 * 8;
            const float b0 = bias[col], b1 = bias[col + 1];
            const float v00 = acc[m2][nt2][0] + b0, v01 = acc[m2][nt2][1] + b1;
            const float v10 = acc[m2][nt2][2] + b0, v11 = acc[m2][nt2][3] + b1;
            if (OUT == 0) {
                float* C = (float*)Cv;
                float* p0 = C + (size_t)(rbase + m2 * 16) * EMB_ + col;
                *(float2*)p0 = make_float2(v00, v01);
                *(float2*)(p0 + 8 * EMB_) = make_float2(v10, v11);
            } else {
                __half* C = (__half*)Cv;
                __half* p0 = C + (size_t)(rbase + m2 * 16) * EMB_ + col;
                *(uint32_t*)p0 = pack_h2(v00, v01);
                *(uint32_t*)(p0 + 8 * EMB_) = pack_h2(v10, v11);
            }
        }
}

struct QKVArgs {
    const __half* ah[3];
    const __half* bh[3];
    const float*  bias[3];
    __half*       c[3];
};

__global__ __launch_bounds__(128)
void gemm_qkv(QKVArgs a)
{
    extern __shared__ char smem[];
    const int z = blockIdx.z;
    gemm_core1<1>(a.ah[z], a.bh[z], a.bias[z], a.c[z], smem);
}

__global__ __launch_bounds__(128)
void gemm_o(const __half* __restrict__ ah, const __half* __restrict__ bh,
            const float* __restrict__ bias, float* __restrict__ c)
{
    extern __shared__ char smem[];
    gemm_core1<0>(ah, bh, bias, c, smem);
}

// ---------------------------------------------------------------------------
// Per-token head-axis attention, fp16 in (row-major), fp16 swizzled out.
// (R9/R13 version: measured 34us)
// ---------------------------------------------------------------------------
__global__ __launch_bounds__(256)
void attn_head_mix(const __half* __restrict__ q, const __half* __restrict__ k,
                   const __half* __restrict__ v, __half* __restrict__ oh)
{
    __shared__ __half sq[NHEAD][72];
    __shared__ __half sk[NHEAD][72];
    __shared__ __half sv[NHEAD][72];
    __shared__ float sa[NHEAD * NHEAD];

    const int t = blockIdx.x;
    const int tid = threadIdx.x;
    const size_t base = (size_t)t * EMB_;

    {
        const int e0 = tid * 4;
        const int h = e0 >> 6, d0 = e0 & 63;
        *(uint2*)&sq[h][d0] = *(const uint2*)(q + base + e0);
        *(uint2*)&sk[h][d0] = *(const uint2*)(k + base + e0);
        *(uint2*)&sv[h][d0] = *(const uint2*)(v + base + e0);
    }
    __syncthreads();

    if (tid < 64) {
        const int h0 = (tid >> 3) << 1;
        const int g0 = (tid & 7) << 1;
        float s00 = 0.f, s01 = 0.f, s10 = 0.f, s11 = 0.f;
#pragma unroll
        for (int d = 0; d < HDIM; d += 2) {
            const float2 qa = __half22float2(*(const __half2*)&sq[h0][d]);
            const float2 qb = __half22float2(*(const __half2*)&sq[h0 + 1][d]);
            const float2 ka = __half22float2(*(const __half2*)&sk[g0][d]);
            const float2 kb = __half22float2(*(const __half2*)&sk[g0 + 1][d]);
            s00 = fmaf(qa.x, ka.x, s00); s00 = fmaf(qa.y, ka.y, s00);
            s01 = fmaf(qa.x, kb.x, s01); s01 = fmaf(qa.y, kb.y, s01);
            s10 = fmaf(qb.x, ka.x, s10); s10 = fmaf(qb.y, ka.y, s10);
            s11 = fmaf(qb.x, kb.x, s11); s11 = fmaf(qb.y, kb.y, s11);
        }
        s00 *= 0.125f; s01 *= 0.125f; s10 *= 0.125f; s11 *= 0.125f;

        float m0 = fmaxf(s00, s01), m1 = fmaxf(s10, s11);
#pragma unroll
        for (int o = 4; o > 0; o >>= 1) {
            m0 = fmaxf(m0, __shfl_xor_sync(0xffffffffu, m0, o, 8));
            m1 = fmaxf(m1, __shfl_xor_sync(0xffffffffu, m1, o, 8));
        }
        const float e00 = __expf(s00 - m0), e01 = __expf(s01 - m0);
        const float e10 = __expf(s10 - m1), e11 = __expf(s11 - m1);
        float u0 = e00 + e01, u1 = e10 + e11;
#pragma unroll
        for (int o = 4; o > 0; o >>= 1) {
            u0 += __shfl_xor_sync(0xffffffffu, u0, o, 8);
            u1 += __shfl_xor_sync(0xffffffffu, u1, o, 8);
        }
        const float r0 = 1.0f / u0, r1 = 1.0f / u1;
        sa[h0 * 16 + g0]           = e00 * r0;
        sa[h0 * 16 + g0 + 1]       = e01 * r0;
        sa[(h0 + 1) * 16 + g0]     = e10 * r1;
        sa[(h0 + 1) * 16 + g0 + 1] = e11 * r1;
    }
    __syncthreads();

    const int ho = tid >> 4;
    const int d0 = (tid & 15) * 4;
    float o4[4] = {0.f, 0.f, 0.f, 0.f};
#pragma unroll
    for (int gg = 0; gg < NHEAD; gg++) {
        const float a = sa[ho * 16 + gg];
        const float2 v0 = __half22float2(*(const __half2*)&sv[gg][d0]);
        const float2 v1 = __half22float2(*(const __half2*)&sv[gg][d0 + 2]);
        o4[0] = fmaf(a, v0.x, o4[0]);
        o4[1] = fmaf(a, v0.y, o4[1]);
        o4[2] = fmaf(a, v1.x, o4[2]);
        o4[3] = fmaf(a, v1.y, o4[3]);
    }

    ushort4 hv;
    hv.x = (unsigned short)(pack_h2(o4[0], 0.f) & 0xFFFF);
    hv.y = (unsigned short)(pack_h2(o4[1], 0.f) & 0xFFFF);
    hv.z = (unsigned short)(pack_h2(o4[2], 0.f) & 0xFFFF);
    hv.w = (unsigned short)(pack_h2(o4[3], 0.f) & 0xFFFF);

    const int chunk = d0 >> 3;
    const size_t off = (((size_t)(t >> 7) * 16 + ho) << 14)
                     + (t & 127) * 128 + ((chunk ^ (t & 7)) << 4) + (d0 & 7) * 2;
    *(ushort4*)((char*)oh + off) = hv;
}

// ---------------------------------------------------------------------------
// Launch
// ---------------------------------------------------------------------------
extern "C" void kernel_launch(void* const* d_in, const int* in_sizes, int n_in,
                              void* d_out, int out_size)
{
    const float* values = (const float*)d_in[0];
    const float* keys   = (const float*)d_in[1];
    const float* query  = (const float*)d_in[2];
    const float* Wv = (const float*)d_in[3];
    const float* bv = (const float*)d_in[4];
    const float* Wk = (const float*)d_in[5];
    const float* bk = (const float*)d_in[6];
    const float* Wq = (const float*)d_in[7];
    const float* bq = (const float*)d_in[8];
    const float* Wo = (const float*)d_in[9];
    const float* bo = (const float*)d_in[10];
    float* out = (float*)d_out;

    static bool attr_set = false;
    if (!attr_set) {
        cudaFuncSetAttribute(gemm_qkv,
                             cudaFuncAttributeMaxDynamicSharedMemorySize, GSMEM);
        cudaFuncSetAttribute(gemm_o,
                             cudaFuncAttributeMaxDynamicSharedMemorySize, GSMEM);
        attr_set = true;
    }

    __half *vh, *kh, *qh, *wvh, *wkh, *wqh, *woh, *ah, *vo, *ko, *qo;
    cudaGetSymbolAddress((void**)&vh, g_vh);
    cudaGetSymbolAddress((void**)&kh, g_kh);
    cudaGetSymbolAddress((void**)&qh, g_qh);
    cudaGetSymbolAddress((void**)&wvh, g_wvh);
    cudaGetSymbolAddress((void**)&wkh, g_wkh);
    cudaGetSymbolAddress((void**)&wqh, g_wqh);
    cudaGetSymbolAddress((void**)&woh, g_woh);
    cudaGetSymbolAddress((void**)&ah, g_ah);
    cudaGetSymbolAddress((void**)&vo, g_vo);
    cudaGetSymbolAddress((void**)&ko, g_ko);
    cudaGetSymbolAddress((void**)&qo, g_qo);

    ConvArgs ca;
    ca.src[0] = values; ca.hi[0] = vh;
    ca.src[1] = keys;   ca.hi[1] = kh;
    ca.src[2] = query;  ca.hi[2] = qh;
    ca.src[3] = nullptr; ca.hi[3] = nullptr;
    conv_act<<<dim3(TOK * 128 / 256, 3), 256>>>(ca);

    ConvArgs cw;
    cw.src[0] = Wq; cw.hi[0] = wqh;
    cw.src[1] = Wk; cw.hi[1] = wkh;
    cw.src[2] = Wv; cw.hi[2] = wvh;
    cw.src[3] = Wo; cw.hi[3] = woh;
    conv_w<<<dim3(EMB_ * 128 / 256, 4), 256>>>(cw);

    QKVArgs a;
    a.ah[0] = qh; a.bh[0] = wqh; a.bias[0] = bq; a.c[0] = qo;
    a.ah[1] = kh; a.bh[1] = wkh; a.bias[1] = bk; a.c[1] = ko;
    a.ah[2] = vh; a.bh[2] = wvh; a.bias[2] = bv; a.c[2] = vo;
    dim3 ggrid(EMB_ / 128, TOK / 128, 3);   // (8, 64, 3)
    gemm_qkv<<<ggrid, 128, GSMEM>>>(a);

    attn_head_mix<<<TOK, 256>>>(qo, ko, vo, ah);

    dim3 ogrid(EMB_ / 128, TOK / 128);      // (8, 64)
    gemm_o<<<ogrid, 128, GSMEM>>>(ah, woh, bo, out);
}

// round 15
// speedup vs baseline: 1.5500x; 1.5500x over previous
#include <cuda_runtime.h>
#include <cuda_fp16.h>
#include <cstdint>

// Problem constants (B=4, S=2048, EMB=1024, HEADS=16, HEAD_DIM=64)
#define TOK   8192
#define EMB_  1024
#define NHEAD 16
#define HDIM  64
#define TILEB 16384          // one 128-row x 128-byte (64 fp16) tile

// ---------------------------------------------------------------------------
// Scratch (device globals). Tiled-swizzled fp16 (GEMM operand layout):
// element (row, col) -> tile (row>>7, col>>6), inside: byte
//   (row&127)*128 + (((col&63)>>3) ^ (row&7))*16 + (col&7)*2
// Plus fp16 row-major q/k/v intermediates.
// ---------------------------------------------------------------------------
__device__ __half g_vh[TOK * EMB_];
__device__ __half g_kh[TOK * EMB_];
__device__ __half g_qh[TOK * EMB_];
__device__ __half g_wvh[EMB_ * EMB_];
__device__ __half g_wkh[EMB_ * EMB_];
__device__ __half g_wqh[EMB_ * EMB_];
__device__ __half g_woh[EMB_ * EMB_];
__device__ __half g_ah[TOK * EMB_];
__device__ __half g_vo[TOK * EMB_];
__device__ __half g_ko[TOK * EMB_];
__device__ __half g_qo[TOK * EMB_];

// ---------------------------------------------------------------------------
// PTX helpers
// ---------------------------------------------------------------------------
__device__ __forceinline__ uint32_t smem_u32(const void* p) {
    uint32_t a;
    asm("{ .reg .u64 t; cvta.to.shared.u64 t, %1; cvt.u32.u64 %0, t; }"
        : "=r"(a) : "l"(p));
    return a;
}

__device__ __forceinline__ uint32_t pack_h2(float a, float b) {
    const __half2 h = __floats2half2_rn(a, b);
    return *(const uint32_t*)&h;
}

#define MBAR_INIT(addr, cnt) \
    asm volatile("mbarrier.init.shared.b64 [%0], %1;" :: "r"(addr), "r"(cnt) : "memory")
#define MBAR_EXPECT_TX(addr, bytes) \
    asm volatile("mbarrier.arrive.expect_tx.shared.b64 _, [%0], %1;" \
                 :: "r"(addr), "r"(bytes) : "memory")
#define MBAR_WAIT(addr, parity) do { \
    uint32_t _m = (addr), _p = (parity), _done; \
    asm volatile("{ .reg .pred p; mbarrier.try_wait.parity.acquire.cta.shared::cta.b64 p, [%1], %2; selp.b32 %0, 1, 0, p; }" \
                 : "=r"(_done) : "r"(_m), "r"(_p) : "memory"); \
    if (!_done) { \
        asm volatile("{ .reg .pred P1; WL_%=: mbarrier.try_wait.parity.acquire.cta.shared::cta.b64 P1, [%0], %1, 0x989680; @P1 bra.uni WD_%=; bra.uni WL_%=; WD_%=: }" \
                     :: "r"(_m), "r"(_p) : "memory"); \
    } \
} while (0)

__device__ __forceinline__ void bulk_g2s(uint32_t dst, const void* src,
                                         uint32_t bytes, uint32_t mbar) {
    asm volatile(
        "cp.async.bulk.shared::cluster.global.mbarrier::complete_tx::bytes [%0], [%1], %2, [%3];"
        :: "r"(dst), "l"(src), "r"(bytes), "r"(mbar) : "memory");
}

#define LDSM4(R, addr) \
    asm volatile("ldmatrix.sync.aligned.m8n8.x4.shared.b16 {%0,%1,%2,%3}, [%4];" \
        : "=r"((R)[0]), "=r"((R)[1]), "=r"((R)[2]), "=r"((R)[3]) : "r"(addr))

#define MMA16816(D, A, B0, B1) \
    asm volatile("mma.sync.aligned.m16n8k16.row.col.f32.f16.f16.f32 " \
        "{%0,%1,%2,%3}, {%4,%5,%6,%7}, {%8,%9}, {%0,%1,%2,%3};" \
        : "+f"((D)[0]), "+f"((D)[1]), "+f"((D)[2]), "+f"((D)[3]) \
        : "r"((A)[0]), "r"((A)[1]), "r"((A)[2]), "r"((A)[3]), "r"(B0), "r"(B1))

// ---------------------------------------------------------------------------
// Conversion: fp32 row-major -> fp16 (round) in tiled-swizzled layout.
// ---------------------------------------------------------------------------
__device__ __forceinline__ void round_store(const float* __restrict__ src,
                                            __half* __restrict__ hi, int gid)
{
    const int row = gid >> 7;
    const int chunk = gid & 127;
    const int col0 = chunk << 3;
    const int kc = col0 >> 6;
    const int c16 = (col0 >> 3) & 7;

    const float4* sp = (const float4*)(src + (size_t)row * EMB_ + col0);
    float x[8];
    *(float4*)&x[0] = sp[0];
    *(float4*)&x[4] = sp[1];

    uint32_t hw[4];
#pragma unroll
    for (int i = 0; i < 4; i++)
        hw[i] = pack_h2(x[2 * i], x[2 * i + 1]);

    const size_t off = (((size_t)(row >> 7) * 16 + kc) << 14)
                     + (row & 127) * 128 + ((c16 ^ (row & 7)) << 4);
    *(uint4*)((char*)hi + off) = make_uint4(hw[0], hw[1], hw[2], hw[3]);
}

struct ConvArgs {
    const float* src[4];
    __half* hi[4];
};

__global__ __launch_bounds__(256)
void conv_act(ConvArgs a)   // grid (4096, 3)
{
    const int z = blockIdx.y;
    const int gid = blockIdx.x * 256 + threadIdx.x;
    round_store(a.src[z], a.hi[z], gid);
}

__global__ __launch_bounds__(256)
void conv_w(ConvArgs a)     // grid (512, 4)
{
    const int z = blockIdx.y;
    const int gid = blockIdx.x * 256 + threadIdx.x;
    round_store(a.src[z], a.hi[z], gid);
}

// ---------------------------------------------------------------------------
// R9 GEMM core (proven): CTA 128x128, 8 warps 4m x 2n (warp 32x64),
// K-chunk 64, 3-stage bulk pipeline, 2 CTAs/SM. fp16 output (row-major).
// ---------------------------------------------------------------------------
#define STAGEB (2 * TILEB)              // 32768
#define GSMEM  (1024 + 3 * STAGEB)      // 99328

__device__ __forceinline__
void gemm_core_qkv(const __half* __restrict__ Ah, const __half* __restrict__ Bh,
                   const float* __restrict__ bias, __half* __restrict__ C,
                   char* smem)
{
    const uint32_t sb = smem_u32(smem);
    const int tid = threadIdx.x;
    const int wid = tid >> 5, lane = tid & 31;
    const int ntb = blockIdx.x, mtb = blockIdx.y;
    const int wm = wid >> 1, wn = wid & 1;

    if (tid == 0) {
        MBAR_INIT(sb + 0, 1);
        MBAR_INIT(sb + 8, 1);
        MBAR_INIT(sb + 16, 1);
    }
    __syncthreads();

    const uint32_t st0 = sb + 1024;
    const char* aH = (const char*)Ah + ((size_t)mtb * 16 << 14);
    const char* bH = (const char*)Bh + ((size_t)ntb * 16 << 14);

    auto load_stage = [&](int kc, int s) {
        const uint32_t full = sb + 8 * s;
        MBAR_EXPECT_TX(full, STAGEB);
        const uint32_t d = st0 + s * STAGEB;
        const size_t o = (size_t)kc << 14;
        bulk_g2s(d,         aH + o, TILEB, full);
        bulk_g2s(d + TILEB, bH + o, TILEB, full);
    };

    if (tid == 0) {
        load_stage(0, 0);
        load_stage(1, 1);
        load_stage(2, 2);
    }

    float acc[2][8][4];
#pragma unroll
    for (int a = 0; a < 2; a++)
#pragma unroll
        for (int b = 0; b < 8; b++)
#pragma unroll
            for (int c = 0; c < 4; c++) acc[a][b][c] = 0.0f;

    const uint32_t la7 = lane & 7;
    const uint32_t a_row = (uint32_t)(wm * 32 + (lane & 15)) * 128;
    const uint32_t a_sel = (lane >> 4);
    const uint32_t b_row = (uint32_t)(wn * 64 + ((lane >> 4) & 1) * 8 + (lane & 7)) * 128;
    const uint32_t b_sel = ((lane >> 3) & 1);

    int s = 0, par = 0;
    for (int kc = 0; kc < 16; kc++) {
        MBAR_WAIT(sb + 8 * s, par);

        const uint32_t st = st0 + s * STAGEB;
        const uint32_t tAH = st;
        const uint32_t tBH = st + TILEB;

#pragma unroll
        for (int ks = 0; ks < 4; ks++) {
            const uint32_t ca = ((uint32_t)(ks * 2) + a_sel) ^ la7;
            const uint32_t cb = ((uint32_t)(ks * 2) + b_sel) ^ la7;
            uint32_t ah[2][4], bh[4][4];
#pragma unroll
            for (int m2 = 0; m2 < 2; m2++)
                LDSM4(ah[m2], tAH + a_row + m2 * 2048 + ca * 16);
#pragma unroll
            for (int n2 = 0; n2 < 4; n2++)
                LDSM4(bh[n2], tBH + b_row + n2 * 2048 + cb * 16);
#pragma unroll
            for (int m2 = 0; m2 < 2; m2++)
#pragma unroll
                for (int n2 = 0; n2 < 4; n2++) {
                    MMA16816(acc[m2][n2 * 2 + 0], ah[m2], bh[n2][0], bh[n2][1]);
                    MMA16816(acc[m2][n2 * 2 + 1], ah[m2], bh[n2][2], bh[n2][3]);
                }
        }
        __syncthreads();
        if (tid == 0 && kc + 3 < 16) load_stage(kc + 3, s);
        if (++s == 3) { s = 0; par ^= 1; }
    }

    const int rbase = mtb * 128 + wm * 32 + (lane >> 2);
    const int cbase = ntb * 128 + wn * 64 + (lane & 3) * 2;
#pragma unroll
    for (int m2 = 0; m2 < 2; m2++)
#pragma unroll
        for (int nt2 = 0; nt2 < 8; nt2++) {
            const int col = cbase + nt2 * 8;
            const float b0 = bias[col], b1 = bias[col + 1];
            __half* p0 = C + (size_t)(rbase + m2 * 16) * EMB_ + col;
            *(uint32_t*)p0 = pack_h2(acc[m2][nt2][0] + b0, acc[m2][nt2][1] + b1);
            *(uint32_t*)(p0 + 8 * EMB_) = pack_h2(acc[m2][nt2][2] + b0, acc[m2][nt2][3] + b1);
        }
}

struct QKVArgs {
    const __half* ah[3];
    const __half* bh[3];
    const float*  bias[3];
    __half*       c[3];
};

__global__ __launch_bounds__(256, 2)
void gemm_qkv(QKVArgs a)
{
    extern __shared__ char smem[];
    const int z = blockIdx.z;
    gemm_core_qkv(a.ah[z], a.bh[z], a.bias[z], a.c[z], smem);
}

// ---------------------------------------------------------------------------
// Fat-warp O-GEMM: CTA 256m x 128n, 8 warps in 4m x 2n, warp tile 64x64
// (128 acc regs), K-chunk 64, 3-stage pipeline, 1 CTA/SM.
// SMEM reads per MMA drop 192B -> 128B (A read 1x at warp level, B read 4x
// over twice the M) -> smem crossbar no longer binding.
// fp32 output.
// ---------------------------------------------------------------------------
#define FSTAGEB (3 * TILEB)             // A: 2 tiles (256 rows) + B: 1 tile
#define FGSMEM  (1024 + 3 * FSTAGEB)    // 148480

__global__ __launch_bounds__(256, 1)
void gemm_o(const __half* __restrict__ Ah, const __half* __restrict__ Bh,
            const float* __restrict__ bias, float* __restrict__ C)
{
    extern __shared__ char smem[];
    const uint32_t sb = smem_u32(smem);
    const int tid = threadIdx.x;
    const int wid = tid >> 5, lane = tid & 31;
    const int ntb = blockIdx.x, mtb = blockIdx.y;   // mtb: 256-row block
    const int wm = wid >> 1, wn = wid & 1;          // 4m x 2n, warp 64x64

    if (tid == 0) {
        MBAR_INIT(sb + 0, 1);
        MBAR_INIT(sb + 8, 1);
        MBAR_INIT(sb + 16, 1);
    }
    __syncthreads();

    const uint32_t st0 = sb + 1024;
    const char* aH0 = (const char*)Ah + ((size_t)(2 * mtb + 0) * 16 << 14);
    const char* aH1 = (const char*)Ah + ((size_t)(2 * mtb + 1) * 16 << 14);
    const char* bH  = (const char*)Bh + ((size_t)ntb * 16 << 14);

    auto load_stage = [&](int kc, int s) {
        const uint32_t full = sb + 8 * s;
        MBAR_EXPECT_TX(full, FSTAGEB);
        const uint32_t d = st0 + s * FSTAGEB;
        const size_t o = (size_t)kc << 14;
        bulk_g2s(d,             aH0 + o, TILEB, full);
        bulk_g2s(d + TILEB,     aH1 + o, TILEB, full);
        bulk_g2s(d + 2 * TILEB, bH  + o, TILEB, full);
    };

    if (tid == 0) {
        load_stage(0, 0);
        load_stage(1, 1);
        load_stage(2, 2);
    }

    float acc[4][8][4];
#pragma unroll
    for (int a = 0; a < 4; a++)
#pragma unroll
        for (int b = 0; b < 8; b++)
#pragma unroll
            for (int c = 0; c < 4; c++) acc[a][b][c] = 0.0f;

    const uint32_t la7 = lane & 7;
    // A: warp rows wm*64..+63 of 256; smem A tile = wm>>1, base row = (wm&1)*64
    const uint32_t a_tile_off = (uint32_t)(wm >> 1) * TILEB;
    const uint32_t a_row = ((uint32_t)((wm & 1) * 64) + (lane & 15)) * 128;
    const uint32_t a_sel = (lane >> 4);
    const uint32_t b_row = (uint32_t)(wn * 64 + ((lane >> 4) & 1) * 8 + (lane & 7)) * 128;
    const uint32_t b_sel = ((lane >> 3) & 1);

    int s = 0, par = 0;
    for (int kc = 0; kc < 16; kc++) {
        MBAR_WAIT(sb + 8 * s, par);

        const uint32_t st = st0 + s * FSTAGEB;
        const uint32_t tAH = st + a_tile_off;
        const uint32_t tBH = st + 2 * TILEB;

#pragma unroll
        for (int ks = 0; ks < 4; ks++) {
            const uint32_t ca = ((uint32_t)(ks * 2) + a_sel) ^ la7;
            const uint32_t cb = ((uint32_t)(ks * 2) + b_sel) ^ la7;
            uint32_t ah[4][4], bh[4][4];
#pragma unroll
            for (int m2 = 0; m2 < 4; m2++)
                LDSM4(ah[m2], tAH + a_row + m2 * 2048 + ca * 16);
#pragma unroll
            for (int n2 = 0; n2 < 4; n2++)
                LDSM4(bh[n2], tBH + b_row + n2 * 2048 + cb * 16);
#pragma unroll
            for (int m2 = 0; m2 < 4; m2++)
#pragma unroll
                for (int n2 = 0; n2 < 4; n2++) {
                    MMA16816(acc[m2][n2 * 2 + 0], ah[m2], bh[n2][0], bh[n2][1]);
                    MMA16816(acc[m2][n2 * 2 + 1], ah[m2], bh[n2][2], bh[n2][3]);
                }
        }
        __syncthreads();
        if (tid == 0 && kc + 3 < 16) load_stage(kc + 3, s);
        if (++s == 3) { s = 0; par ^= 1; }
    }

    const int rbase = mtb * 256 + wm * 64 + (lane >> 2);
    const int cbase = ntb * 128 + wn * 64 + (lane & 3) * 2;
#pragma unroll
    for (int m2 = 0; m2 < 4; m2++)
#pragma unroll
        for (int nt2 = 0; nt2 < 8; nt2++) {
            const int col = cbase + nt2 * 8;
            const float b0 = bias[col], b1 = bias[col + 1];
            float* p0 = C + (size_t)(rbase + m2 * 16) * EMB_ + col;
            *(float2*)p0 = make_float2(acc[m2][nt2][0] + b0, acc[m2][nt2][1] + b1);
            *(float2*)(p0 + 8 * EMB_) = make_float2(acc[m2][nt2][2] + b0, acc[m2][nt2][3] + b1);
        }
}

// ---------------------------------------------------------------------------
// Per-token head-axis attention, fp16 in (row-major), fp16 swizzled out.
// (R9 version, measured 34us)
// ---------------------------------------------------------------------------
__global__ __launch_bounds__(256)
void attn_head_mix(const __half* __restrict__ q, const __half* __restrict__ k,
                   const __half* __restrict__ v, __half* __restrict__ oh)
{
    __shared__ __half sq[NHEAD][72];
    __shared__ __half sk[NHEAD][72];
    __shared__ __half sv[NHEAD][72];
    __shared__ float sa[NHEAD * NHEAD];

    const int t = blockIdx.x;
    const int tid = threadIdx.x;
    const size_t base = (size_t)t * EMB_;

    {
        const int e0 = tid * 4;
        const int h = e0 >> 6, d0 = e0 & 63;
        *(uint2*)&sq[h][d0] = *(const uint2*)(q + base + e0);
        *(uint2*)&sk[h][d0] = *(const uint2*)(k + base + e0);
        *(uint2*)&sv[h][d0] = *(const uint2*)(v + base + e0);
    }
    __syncthreads();

    if (tid < 64) {
        const int h0 = (tid >> 3) << 1;
        const int g0 = (tid & 7) << 1;
        float s00 = 0.f, s01 = 0.f, s10 = 0.f, s11 = 0.f;
#pragma unroll
        for (int d = 0; d < HDIM; d += 2) {
            const float2 qa = __half22float2(*(const __half2*)&sq[h0][d]);
            const float2 qb = __half22float2(*(const __half2*)&sq[h0 + 1][d]);
            const float2 ka = __half22float2(*(const __half2*)&sk[g0][d]);
            const float2 kb = __half22float2(*(const __half2*)&sk[g0 + 1][d]);
            s00 = fmaf(qa.x, ka.x, s00); s00 = fmaf(qa.y, ka.y, s00);
            s01 = fmaf(qa.x, kb.x, s01); s01 = fmaf(qa.y, kb.y, s01);
            s10 = fmaf(qb.x, ka.x, s10); s10 = fmaf(qb.y, ka.y, s10);
            s11 = fmaf(qb.x, kb.x, s11); s11 = fmaf(qb.y, kb.y, s11);
        }
        s00 *= 0.125f; s01 *= 0.125f; s10 *= 0.125f; s11 *= 0.125f;

        float m0 = fmaxf(s00, s01), m1 = fmaxf(s10, s11);
#pragma unroll
        for (int o = 4; o > 0; o >>= 1) {
            m0 = fmaxf(m0, __shfl_xor_sync(0xffffffffu, m0, o, 8));
            m1 = fmaxf(m1, __shfl_xor_sync(0xffffffffu, m1, o, 8));
        }
        const float e00 = __expf(s00 - m0), e01 = __expf(s01 - m0);
        const float e10 = __expf(s10 - m1), e11 = __expf(s11 - m1);
        float u0 = e00 + e01, u1 = e10 + e11;
#pragma unroll
        for (int o = 4; o > 0; o >>= 1) {
            u0 += __shfl_xor_sync(0xffffffffu, u0, o, 8);
            u1 += __shfl_xor_sync(0xffffffffu, u1, o, 8);
        }
        const float r0 = 1.0f / u0, r1 = 1.0f / u1;
        sa[h0 * 16 + g0]           = e00 * r0;
        sa[h0 * 16 + g0 + 1]       = e01 * r0;
        sa[(h0 + 1) * 16 + g0]     = e10 * r1;
        sa[(h0 + 1) * 16 + g0 + 1] = e11 * r1;
    }
    __syncthreads();

    const int ho = tid >> 4;
    const int d0 = (tid & 15) * 4;
    float o4[4] = {0.f, 0.f, 0.f, 0.f};
#pragma unroll
    for (int gg = 0; gg < NHEAD; gg++) {
        const float a = sa[ho * 16 + gg];
        const float2 v0 = __half22float2(*(const __half2*)&sv[gg][d0]);
        const float2 v1 = __half22float2(*(const __half2*)&sv[gg][d0 + 2]);
        o4[0] = fmaf(a, v0.x, o4[0]);
        o4[1] = fmaf(a, v0.y, o4[1]);
        o4[2] = fmaf(a, v1.x, o4[2]);
        o4[3] = fmaf(a, v1.y, o4[3]);
    }

    ushort4 hv;
    hv.x = (unsigned short)(pack_h2(o4[0], 0.f) & 0xFFFF);
    hv.y = (unsigned short)(pack_h2(o4[1], 0.f) & 0xFFFF);
    hv.z = (unsigned short)(pack_h2(o4[2], 0.f) & 0xFFFF);
    hv.w = (unsigned short)(pack_h2(o4[3], 0.f) & 0xFFFF);

    const int chunk = d0 >> 3;
    const size_t off = (((size_t)(t >> 7) * 16 + ho) << 14)
                     + (t & 127) * 128 + ((chunk ^ (t & 7)) << 4) + (d0 & 7) * 2;
    *(ushort4*)((char*)oh + off) = hv;
}

// ---------------------------------------------------------------------------
// Launch
// ---------------------------------------------------------------------------
extern "C" void kernel_launch(void* const* d_in, const int* in_sizes, int n_in,
                              void* d_out, int out_size)
{
    const float* values = (const float*)d_in[0];
    const float* keys   = (const float*)d_in[1];
    const float* query  = (const float*)d_in[2];
    const float* Wv = (const float*)d_in[3];
    const float* bv = (const float*)d_in[4];
    const float* Wk = (const float*)d_in[5];
    const float* bk = (const float*)d_in[6];
    const float* Wq = (const float*)d_in[7];
    const float* bq = (const float*)d_in[8];
    const float* Wo = (const float*)d_in[9];
    const float* bo = (const float*)d_in[10];
    float* out = (float*)d_out;

    static bool attr_set = false;
    if (!attr_set) {
        cudaFuncSetAttribute(gemm_qkv,
                             cudaFuncAttributeMaxDynamicSharedMemorySize, GSMEM);
        cudaFuncSetAttribute(gemm_o,
                             cudaFuncAttributeMaxDynamicSharedMemorySize, FGSMEM);
        attr_set = true;
    }

    __half *vh, *kh, *qh, *wvh, *wkh, *wqh, *woh, *ah, *vo, *ko, *qo;
    cudaGetSymbolAddress((void**)&vh, g_vh);
    cudaGetSymbolAddress((void**)&kh, g_kh);
    cudaGetSymbolAddress((void**)&qh, g_qh);
    cudaGetSymbolAddress((void**)&wvh, g_wvh);
    cudaGetSymbolAddress((void**)&wkh, g_wkh);
    cudaGetSymbolAddress((void**)&wqh, g_wqh);
    cudaGetSymbolAddress((void**)&woh, g_woh);
    cudaGetSymbolAddress((void**)&ah, g_ah);
    cudaGetSymbolAddress((void**)&vo, g_vo);
    cudaGetSymbolAddress((void**)&ko, g_ko);
    cudaGetSymbolAddress((void**)&qo, g_qo);

    ConvArgs ca;
    ca.src[0] = values; ca.hi[0] = vh;
    ca.src[1] = keys;   ca.hi[1] = kh;
    ca.src[2] = query;  ca.hi[2] = qh;
    ca.src[3] = nullptr; ca.hi[3] = nullptr;
    conv_act<<<dim3(TOK * 128 / 256, 3), 256>>>(ca);

    ConvArgs cw;
    cw.src[0] = Wq; cw.hi[0] = wqh;
    cw.src[1] = Wk; cw.hi[1] = wkh;
    cw.src[2] = Wv; cw.hi[2] = wvh;
    cw.src[3] = Wo; cw.hi[3] = woh;
    conv_w<<<dim3(EMB_ * 128 / 256, 4), 256>>>(cw);

    QKVArgs a;
    a.ah[0] = qh; a.bh[0] = wqh; a.bias[0] = bq; a.c[0] = qo;
    a.ah[1] = kh; a.bh[1] = wkh; a.bias[1] = bk; a.c[1] = ko;
    a.ah[2] = vh; a.bh[2] = wvh; a.bias[2] = bv; a.c[2] = vo;
    dim3 ggrid(EMB_ / 128, TOK / 128, 3);   // (8, 64, 3)
    gemm_qkv<<<ggrid, 256, GSMEM>>>(a);

    attn_head_mix<<<TOK, 256>>>(qo, ko, vo, ah);

    dim3 ogrid(EMB_ / 128, TOK / 256);      // (8, 32)
    gemm_o<<<ogrid, 256, FGSMEM>>>(ah, woh, bo, out);
}